// round 12
// baseline (speedup 1.0000x reference)
#include <cuda_runtime.h>
#include <cuda_fp16.h>
#include <cstdint>

#define NODE_NUM 100000
#define BATCH 4096
#define LAYERS 4
#define EMB 128
#define FEAT 256
#define NEIGH 32
#define PAIRS (BATCH*LAYERS)   // 16384

// Scratch (device globals: allocation-free rule)
__device__ __align__(16) __half g_featsh[NODE_NUM * FEAT];  // 51.2 MB
__device__ __align__(16) float  g_h[PAIRS * EMB];           // 8 MB  (fp32 h)
__device__ __align__(16) __half g_hh[PAIRS * EMB];          // 4 MB  (fp16 h)
__device__ __align__(16) __half g_neth[LAYERS * FEAT * EMB];// 256 KB
__device__ __align__(16) __half g_ws1h[EMB * EMB];          // 32 KB

// ---------------------------------------------------------------------------
// helpers
// ---------------------------------------------------------------------------
__device__ __forceinline__ uint32_t s2u(const void* p) {
    return (uint32_t)__cvta_generic_to_shared(p);
}
__device__ __forceinline__ void ldm4(uint32_t& r0, uint32_t& r1, uint32_t& r2,
                                     uint32_t& r3, uint32_t addr) {
    asm volatile("ldmatrix.sync.aligned.m8n8.x4.shared.b16 {%0,%1,%2,%3},[%4];"
                 : "=r"(r0), "=r"(r1), "=r"(r2), "=r"(r3) : "r"(addr));
}
__device__ __forceinline__ void ldm4t(uint32_t& r0, uint32_t& r1, uint32_t& r2,
                                      uint32_t& r3, uint32_t addr) {
    asm volatile("ldmatrix.sync.aligned.m8n8.x4.trans.shared.b16 {%0,%1,%2,%3},[%4];"
                 : "=r"(r0), "=r"(r1), "=r"(r2), "=r"(r3) : "r"(addr));
}
__device__ __forceinline__ void mma16816(float* c, uint32_t a0, uint32_t a1,
                                         uint32_t a2, uint32_t a3,
                                         uint32_t b0, uint32_t b1) {
    asm volatile(
        "mma.sync.aligned.m16n8k16.row.col.f32.f16.f16.f32 "
        "{%0,%1,%2,%3},{%4,%5,%6,%7},{%8,%9},{%0,%1,%2,%3};"
        : "+f"(c[0]), "+f"(c[1]), "+f"(c[2]), "+f"(c[3])
        : "r"(a0), "r"(a1), "r"(a2), "r"(a3), "r"(b0), "r"(b1));
}
__device__ __forceinline__ uint32_t h2u(float a, float b) {
    __half2 h = __floats2half2_rn(a, b);
    return *(uint32_t*)&h;
}

// ---------------------------------------------------------------------------
// K0: features fp32 -> fp16
// ---------------------------------------------------------------------------
__global__ __launch_bounds__(256) void k0_convert(const float* __restrict__ feats) {
    const int stride = gridDim.x * blockDim.x;
    const float4* __restrict__ src = (const float4*)feats;
    uint2* __restrict__ dst = (uint2*)g_featsh;
    const int total4 = NODE_NUM * FEAT / 4;
    for (int k = blockIdx.x * blockDim.x + threadIdx.x; k < total4; k += stride) {
        const float4 v = src[k];
        uint2 o; o.x = h2u(v.x, v.y); o.y = h2u(v.z, v.w);
        dst[k] = o;
    }
}

// ---------------------------------------------------------------------------
// K0b: convert net [4][256][128] and Ws1 [128][128] to fp16.
// ---------------------------------------------------------------------------
__global__ __launch_bounds__(256) void k0b_convert(const float* __restrict__ net,
                                                   const float* __restrict__ ws1) {
    const int t = blockIdx.x * blockDim.x + threadIdx.x;
    const int netN4 = LAYERS * FEAT * EMB / 4;             // 32768
    if (t < netN4) {
        const float4 v = ((const float4*)net)[t];
        uint2 o; o.x = h2u(v.x, v.y); o.y = h2u(v.z, v.w);
        ((uint2*)g_neth)[t] = o;
    } else {
        const int u = t - netN4;
        const float4 v = ((const float4*)ws1)[u];
        uint2 o; o.x = h2u(v.x, v.y); o.y = h2u(v.z, v.w);
        ((uint2*)g_ws1h)[u] = o;
    }
}

// ---------------------------------------------------------------------------
// K12 (fused gather + GEMM): grid (64, 4), block 256 (8 warps).
// Phase G: warp w gathers+sums 8 pairs (rows w*8..w*8+7), packs fp16 into
//          registers pk[8] (each lane: dims lane*8..lane*8+7).
// Phase M: HMMA mainloop over 4 K-chunks of 64; A chunk c comes from lanes
//          with lane>>3==c storing pk to smem; B chunk register-prefetched.
// ---------------------------------------------------------------------------
__global__ __launch_bounds__(256) void k12_fused(const int* __restrict__ neighs) {
    __shared__ __align__(16) __half Ah[64][72];    // 9216 B (per-chunk A)
    __shared__ __align__(16) __half Bh[64][136];   // 17408 B

    const int l  = blockIdx.y;
    const int bm = blockIdx.x;
    const int tid = threadIdx.x;
    const int w = tid >> 5, lane = tid & 31;
    const int m0 = (w & 3) * 16;
    const int n0 = (w >> 2) * 64;
    const int lq = lane >> 3, lr = lane & 7;
    const int g = lane >> 2, t = lane & 3;

    // ---- phase G: gather + sum 8 pairs, pack fp16 in registers ----
    uint4 pk[8];
    {
        const float4* __restrict__ base = (const float4*)g_featsh;
        #pragma unroll
        for (int i = 0; i < 8; i++) {
            const int row = w * 8 + i;
            const int pair = (bm * 64 + row) * 4 + l;
            const int myidx = neighs[pair * 32 + lane];
            float acc[8];
            #pragma unroll
            for (int q = 0; q < 8; q++) acc[q] = 0.f;
            #pragma unroll
            for (int j = 0; j < NEIGH; j++) {
                const int n = __shfl_sync(0xffffffffu, myidx, j);
                const float4 v = base[n * 32 + lane];
                const half2* h2p = (const half2*)&v;
                #pragma unroll
                for (int q = 0; q < 4; q++) {
                    const float2 f = __half22float2(h2p[q]);
                    acc[2 * q]     += f.x;
                    acc[2 * q + 1] += f.y;
                }
            }
            pk[i].x = h2u(acc[0], acc[1]); pk[i].y = h2u(acc[2], acc[3]);
            pk[i].z = h2u(acc[4], acc[5]); pk[i].w = h2u(acc[6], acc[7]);
        }
    }

    // ---- phase M: HMMA GEMM over 4 K-chunks ----
    int rB[4], cB[4];
    #pragma unroll
    for (int i = 0; i < 4; i++) {
        const int u = tid + i * 256;
        rB[i] = u >> 4; cB[i] = u & 15;
    }
    const __half* __restrict__ netl = g_neth + l * FEAT * EMB;

    float accm[8][4];
    #pragma unroll
    for (int i = 0; i < 8; i++)
        #pragma unroll
        for (int j = 0; j < 4; j++) accm[i][j] = 0.f;

    uint4 pB[4];
    #pragma unroll
    for (int i = 0; i < 4; i++)
        pB[i] = *(const uint4*)&netl[rB[i] * EMB + cB[i] * 8];

    for (int c = 0; c < 4; c++) {
        // store A chunk c (lanes owning dims 64c..64c+63) + B chunk c
        if (lq == c) {
            #pragma unroll
            for (int i = 0; i < 8; i++)
                *(uint4*)&Ah[w * 8 + i][lr * 8] = pk[i];
        }
        #pragma unroll
        for (int i = 0; i < 4; i++) *(uint4*)&Bh[rB[i]][cB[i] * 8] = pB[i];
        __syncthreads();
        // prefetch next B chunk (overlaps mma)
        if (c < 3) {
            const int kb = (c + 1) * 64;
            #pragma unroll
            for (int i = 0; i < 4; i++)
                pB[i] = *(const uint4*)&netl[(kb + rB[i]) * EMB + cB[i] * 8];
        }
        #pragma unroll
        for (int ks = 0; ks < 4; ks++) {
            const int kc = ks * 16;
            uint32_t a0, a1, a2, a3;
            ldm4(a0, a1, a2, a3,
                 s2u(&Ah[m0 + lr + (lq & 1) * 8][kc + (lq >> 1) * 8]));
            #pragma unroll
            for (int jn = 0; jn < 4; jn++) {
                uint32_t b0, b1, b2, b3;
                ldm4t(b0, b1, b2, b3,
                      s2u(&Bh[kc + lr + (lq & 1) * 8][n0 + jn * 16 + (lq >> 1) * 8]));
                mma16816(accm[2 * jn],     a0, a1, a2, a3, b0, b1);
                mma16816(accm[2 * jn + 1], a0, a1, a2, a3, b2, b3);
            }
        }
        __syncthreads();
    }

    // epilogue: write fp32 + fp16 h
    #pragma unroll
    for (int jn2 = 0; jn2 < 8; jn2++) {
        const int col = n0 + jn2 * 8 + 2 * t;
        const int row0 = bm * 64 + m0 + g;
        const int pair0 = row0 * 4 + l;
        const int pair1 = (row0 + 8) * 4 + l;
        *(float2*)&g_h[pair0 * EMB + col] = make_float2(accm[jn2][0], accm[jn2][1]);
        *(float2*)&g_h[pair1 * EMB + col] = make_float2(accm[jn2][2], accm[jn2][3]);
        *(uint32_t*)&g_hh[pair0 * EMB + col] = h2u(accm[jn2][0], accm[jn2][1]);
        *(uint32_t*)&g_hh[pair1 * EMB + col] = h2u(accm[jn2][2], accm[jn2][3]);
    }
}

// ---------------------------------------------------------------------------
// K34: tile = 64 pairs (16 batch rows), grid 256 blocks, 256 threads.
// phase1: HMMA scores GEMM with register prefetch of chunk 1.
// ---------------------------------------------------------------------------
__global__ __launch_bounds__(256) void k34_fused(const float* __restrict__ Ws2,
                                                 const float* __restrict__ TW,
                                                 const float* __restrict__ lemb,
                                                 const int* __restrict__ node_i,
                                                 const int* __restrict__ layers,
                                                 float* __restrict__ out) {
    __shared__ __align__(16) unsigned char SB[36608];
    __half (*Ah)[72]   = (__half(*)[72])(SB + 0);        // 9216 B  (phase1)
    __half (*Bh)[136]  = (__half(*)[136])(SB + 9216);    // 17408 B (phase1)
    float (*Bs4)[128]  = (float(*)[128])(SB + 0);        // 16384 B (phase4, reuse)
    float (*aggs)[132] = (float(*)[132])(SB + 26624);    // 8448 B
    float (*red)[2]    = (float(*)[2])(SB + 35072);      // 512 B
    float *scr         = (float*)(SB + 35584);           // 256 B
    float (*att)[4]    = (float(*)[4])(SB + 35840);      // 256 B
    float *w2s         = (float*)(SB + 36096);           // 512 B

    const int tid = threadIdx.x;
    const int bm = blockIdx.x;          // 256 blocks
    const int pb = bm * 64;             // pair base
    const int B0 = bm * 16;             // batch-row base

    const int w = tid >> 5, lane = tid & 31;
    const int m0 = (w & 3) * 16;
    const int nh = w >> 2;
    const int n0 = nh * 64;
    const int lq = lane >> 3, lr = lane & 7;
    const int g = lane >> 2, t = lane & 3;

    if (tid < 128) w2s[tid] = Ws2[tid];

    // staging indices
    const int uA0 = tid,        rA0 = uA0 >> 3, cA0 = uA0 & 7;
    const int uA1 = tid + 256,  rA1 = uA1 >> 3, cA1 = uA1 & 7;
    int rB[4], cB[4];
    #pragma unroll
    for (int i = 0; i < 4; i++) {
        const int u = tid + i * 256;
        rB[i] = u >> 4; cB[i] = u & 15;
    }

    // ---- phase 1: HMMA GEMM h[64x128] @ Ws1[128x128], 2 K-chunks + prefetch --
    float acc[8][4];
    #pragma unroll
    for (int i = 0; i < 8; i++)
        #pragma unroll
        for (int j = 0; j < 4; j++) acc[i][j] = 0.f;

    uint4 pA0, pA1, pB[4];
    pA0 = *(const uint4*)&g_hh[(pb + rA0) * EMB + cA0 * 8];
    pA1 = *(const uint4*)&g_hh[(pb + rA1) * EMB + cA1 * 8];
    #pragma unroll
    for (int i = 0; i < 4; i++)
        pB[i] = *(const uint4*)&g_ws1h[rB[i] * EMB + cB[i] * 8];
    *(uint4*)&Ah[rA0][cA0 * 8] = pA0;
    *(uint4*)&Ah[rA1][cA1 * 8] = pA1;
    #pragma unroll
    for (int i = 0; i < 4; i++) *(uint4*)&Bh[rB[i]][cB[i] * 8] = pB[i];
    __syncthreads();

    for (int c = 0; c < 2; c++) {
        if (c < 1) {
            pA0 = *(const uint4*)&g_hh[(pb + rA0) * EMB + 64 + cA0 * 8];
            pA1 = *(const uint4*)&g_hh[(pb + rA1) * EMB + 64 + cA1 * 8];
            #pragma unroll
            for (int i = 0; i < 4; i++)
                pB[i] = *(const uint4*)&g_ws1h[(64 + rB[i]) * EMB + cB[i] * 8];
        }
        #pragma unroll
        for (int ks = 0; ks < 4; ks++) {
            const int kc = ks * 16;
            uint32_t a0, a1, a2, a3;
            ldm4(a0, a1, a2, a3,
                 s2u(&Ah[m0 + lr + (lq & 1) * 8][kc + (lq >> 1) * 8]));
            #pragma unroll
            for (int jn = 0; jn < 4; jn++) {
                uint32_t b0, b1, b2, b3;
                ldm4t(b0, b1, b2, b3,
                      s2u(&Bh[kc + lr + (lq & 1) * 8][n0 + jn * 16 + (lq >> 1) * 8]));
                mma16816(acc[2 * jn],     a0, a1, a2, a3, b0, b1);
                mma16816(acc[2 * jn + 1], a0, a1, a2, a3, b2, b3);
            }
        }
        __syncthreads();
        if (c < 1) {
            *(uint4*)&Ah[rA0][cA0 * 8] = pA0;
            *(uint4*)&Ah[rA1][cA1 * 8] = pA1;
            #pragma unroll
            for (int i = 0; i < 4; i++) *(uint4*)&Bh[rB[i]][cB[i] * 8] = pB[i];
            __syncthreads();
        }
    }
    // epilogue: tanh + dot with Ws2, reduce over quad lanes
    {
        float p0 = 0.f, p1 = 0.f;
        #pragma unroll
        for (int jn2 = 0; jn2 < 8; jn2++) {
            const int col = n0 + jn2 * 8 + 2 * t;
            p0 += tanhf(acc[jn2][0]) * w2s[col] + tanhf(acc[jn2][1]) * w2s[col + 1];
            p1 += tanhf(acc[jn2][2]) * w2s[col] + tanhf(acc[jn2][3]) * w2s[col + 1];
        }
        p0 += __shfl_xor_sync(0xffffffffu, p0, 1);
        p0 += __shfl_xor_sync(0xffffffffu, p0, 2);
        p1 += __shfl_xor_sync(0xffffffffu, p1, 1);
        p1 += __shfl_xor_sync(0xffffffffu, p1, 2);
        if (t == 0) {
            red[m0 + g][nh]     = p0;
            red[m0 + 8 + g][nh] = p1;
        }
    }
    __syncthreads();
    if (tid < 64) scr[tid] = red[tid][0] + red[tid][1];
    __syncthreads();

    // ---- phase 2: softmax over 4 layers (16 rows) ----
    if (tid < 16) {
        const float s0 = scr[tid * 4 + 0];
        const float s1 = scr[tid * 4 + 1];
        const float s2 = scr[tid * 4 + 2];
        const float s3 = scr[tid * 4 + 3];
        const float mx = fmaxf(fmaxf(s0, s1), fmaxf(s2, s3));
        const float e0 = __expf(s0 - mx), e1 = __expf(s1 - mx);
        const float e2 = __expf(s2 - mx), e3 = __expf(s3 - mx);
        const float inv = 1.f / (e0 + e1 + e2 + e3);
        att[tid][0] = e0 * inv; att[tid][1] = e1 * inv;
        att[tid][2] = e2 * inv; att[tid][3] = e3 * inv;
    }
    __syncthreads();

    // ---- phase 3: attention-weighted aggregation (fp32 h) ----
    {
        const int m = tid & 127;
        const int bh = tid >> 7;
        #pragma unroll
        for (int tt = 0; tt < 8; tt++) {
            const int b = bh * 8 + tt;
            const int base = (pb + b * 4) * EMB + m;
            float a = att[b][0] * g_h[base];
            a = fmaf(att[b][1], g_h[base + EMB], a);
            a = fmaf(att[b][2], g_h[base + 2 * EMB], a);
            a = fmaf(att[b][3], g_h[base + 3 * EMB], a);
            aggs[b][m] = a;
        }
    }
    __syncthreads();

    // ---- phase 4: ne = agg @ TW (16x128 @ 128x128), fp32 ----
    const int wr = tid >> 5;
    const int wc = tid & 31;
    float pa[2][4];
    #pragma unroll
    for (int i = 0; i < 2; i++)
        #pragma unroll
        for (int j = 0; j < 4; j++) pa[i][j] = 0.f;

    for (int kc = 0; kc < 4; kc++) {
        #pragma unroll
        for (int i = 0; i < 16; i++) {
            const int idx = tid + i * 256;
            const int f = idx >> 7, m = idx & 127;
            Bs4[f][m] = TW[(kc * 32 + f) * EMB + m];
        }
        __syncthreads();
        #pragma unroll
        for (int kk = 0; kk < 32; kk++) {
            const int k = kc * 32 + kk;
            const float a0 = aggs[wr * 2][k];
            const float a1 = aggs[wr * 2 + 1][k];
            const float4 bv = *(const float4*)&Bs4[kk][wc * 4];
            pa[0][0] = fmaf(a0, bv.x, pa[0][0]); pa[0][1] = fmaf(a0, bv.y, pa[0][1]);
            pa[0][2] = fmaf(a0, bv.z, pa[0][2]); pa[0][3] = fmaf(a0, bv.w, pa[0][3]);
            pa[1][0] = fmaf(a1, bv.x, pa[1][0]); pa[1][1] = fmaf(a1, bv.y, pa[1][1]);
            pa[1][2] = fmaf(a1, bv.z, pa[1][2]); pa[1][3] = fmaf(a1, bv.w, pa[1][3]);
        }
        __syncthreads();
    }

    // ---- phase 5: residual + L2 normalize (warp-local) ----
    #pragma unroll
    for (int i = 0; i < 2; i++) {
        const int bg = B0 + wr * 2 + i;
        const int li = node_i[bg] * 4 + layers[bg];
        const float4 lv = *(const float4*)&lemb[li * EMB + wc * 4];
        float f[4];
        f[0] = pa[i][0] + lv.x;
        f[1] = pa[i][1] + lv.y;
        f[2] = pa[i][2] + lv.z;
        f[3] = pa[i][3] + lv.w;
        float v = f[0]*f[0] + f[1]*f[1] + f[2]*f[2] + f[3]*f[3];
        #pragma unroll
        for (int off = 16; off > 0; off >>= 1)
            v += __shfl_xor_sync(0xffffffffu, v, off);
        const float inv = 1.f / fmaxf(sqrtf(v), 1e-12f);
        float4 o;
        o.x = f[0] * inv; o.y = f[1] * inv; o.z = f[2] * inv; o.w = f[3] * inv;
        *(float4*)&out[bg * EMB + wc * 4] = o;
    }
}

// ---------------------------------------------------------------------------
extern "C" void kernel_launch(void* const* d_in, const int* in_sizes, int n_in,
                              void* d_out, int out_size) {
    const int*   layers  = (const int*)d_in[0];
    const int*   node_i  = (const int*)d_in[1];
    const int*   neighs  = (const int*)d_in[2];
    const float* feats   = (const float*)d_in[3];
    const float* lemb    = (const float*)d_in[4];
    const float* net     = (const float*)d_in[5];
    const float* TW      = (const float*)d_in[6];
    const float* Ws1     = (const float*)d_in[7];
    const float* Ws2     = (const float*)d_in[8];
    float* out = (float*)d_out;

    k0_convert<<<2048, 256>>>(feats);
    k0b_convert<<<144, 256>>>(net, Ws1);
    k12_fused<<<dim3(BATCH / 64, LAYERS), 256>>>(neighs);
    k34_fused<<<PAIRS / 64, 256>>>(Ws2, TW, lemb, node_i, layers, out);
}

// round 14
// speedup vs baseline: 1.0912x; 1.0912x over previous
#include <cuda_runtime.h>
#include <cuda_fp16.h>
#include <cstdint>

#define NODE_NUM 100000
#define BATCH 4096
#define LAYERS 4
#define EMB 128
#define FEAT 256
#define NEIGH 32
#define PAIRS (BATCH*LAYERS)   // 16384

typedef unsigned long long u64;

// Scratch (device globals: allocation-free rule)
__device__ __align__(16) __half g_featsh[NODE_NUM * FEAT];  // 51.2 MB
__device__ __align__(16) __half g_sumfh[PAIRS * FEAT];      // 8 MB  (fp16 sumfeat)
__device__ __align__(16) float  g_h[PAIRS * EMB];           // 8 MB  (fp32 h)
__device__ __align__(16) __half g_hh[PAIRS * EMB];          // 4 MB  (fp16 h)
__device__ __align__(16) __half g_neth[LAYERS * FEAT * EMB];// 256 KB
__device__ __align__(16) __half g_ws1h[EMB * EMB];          // 32 KB

// ---------------------------------------------------------------------------
// helpers
// ---------------------------------------------------------------------------
__device__ __forceinline__ uint32_t s2u(const void* p) {
    return (uint32_t)__cvta_generic_to_shared(p);
}
__device__ __forceinline__ void ldm4(uint32_t& r0, uint32_t& r1, uint32_t& r2,
                                     uint32_t& r3, uint32_t addr) {
    asm volatile("ldmatrix.sync.aligned.m8n8.x4.shared.b16 {%0,%1,%2,%3},[%4];"
                 : "=r"(r0), "=r"(r1), "=r"(r2), "=r"(r3) : "r"(addr));
}
__device__ __forceinline__ void ldm4t(uint32_t& r0, uint32_t& r1, uint32_t& r2,
                                      uint32_t& r3, uint32_t addr) {
    asm volatile("ldmatrix.sync.aligned.m8n8.x4.trans.shared.b16 {%0,%1,%2,%3},[%4];"
                 : "=r"(r0), "=r"(r1), "=r"(r2), "=r"(r3) : "r"(addr));
}
__device__ __forceinline__ void mma16816(float* c, uint32_t a0, uint32_t a1,
                                         uint32_t a2, uint32_t a3,
                                         uint32_t b0, uint32_t b1) {
    asm volatile(
        "mma.sync.aligned.m16n8k16.row.col.f32.f16.f16.f32 "
        "{%0,%1,%2,%3},{%4,%5,%6,%7},{%8,%9},{%0,%1,%2,%3};"
        : "+f"(c[0]), "+f"(c[1]), "+f"(c[2]), "+f"(c[3])
        : "r"(a0), "r"(a1), "r"(a2), "r"(a3), "r"(b0), "r"(b1));
}
__device__ __forceinline__ uint32_t h2u(float a, float b) {
    __half2 h = __floats2half2_rn(a, b);
    return *(uint32_t*)&h;
}
__device__ __forceinline__ u64 pack2(float x) {
    u64 r; asm("mov.b64 %0,{%1,%1};" : "=l"(r) : "f"(x)); return r;
}
__device__ __forceinline__ u64 fma2(u64 a, u64 b, u64 c) {
    u64 d; asm("fma.rn.f32x2 %0,%1,%2,%3;" : "=l"(d) : "l"(a), "l"(b), "l"(c)); return d;
}
__device__ __forceinline__ float2 unpk(u64 v) {
    float lo, hi; asm("mov.b64 {%0,%1},%2;" : "=f"(lo), "=f"(hi) : "l"(v));
    return make_float2(lo, hi);
}

// ---------------------------------------------------------------------------
// K0: features fp32 -> fp16
// ---------------------------------------------------------------------------
__global__ __launch_bounds__(256) void k0_convert(const float* __restrict__ feats) {
    const int stride = gridDim.x * blockDim.x;
    const float4* __restrict__ src = (const float4*)feats;
    uint2* __restrict__ dst = (uint2*)g_featsh;
    const int total4 = NODE_NUM * FEAT / 4;
    for (int k = blockIdx.x * blockDim.x + threadIdx.x; k < total4; k += stride) {
        const float4 v = src[k];
        uint2 o; o.x = h2u(v.x, v.y); o.y = h2u(v.z, v.w);
        dst[k] = o;
    }
}

// ---------------------------------------------------------------------------
// K0b: convert net [4][256][128] and Ws1 [128][128] to fp16.
// ---------------------------------------------------------------------------
__global__ __launch_bounds__(256) void k0b_convert(const float* __restrict__ net,
                                                   const float* __restrict__ ws1) {
    const int t = blockIdx.x * blockDim.x + threadIdx.x;
    const int netN4 = LAYERS * FEAT * EMB / 4;             // 32768
    if (t < netN4) {
        const float4 v = ((const float4*)net)[t];
        uint2 o; o.x = h2u(v.x, v.y); o.y = h2u(v.z, v.w);
        ((uint2*)g_neth)[t] = o;
    } else {
        const int u = t - netN4;
        const float4 v = ((const float4*)ws1)[u];
        uint2 o; o.x = h2u(v.x, v.y); o.y = h2u(v.z, v.w);
        ((uint2*)g_ws1h)[u] = o;
    }
}

// ---------------------------------------------------------------------------
// K1: fp16 gather + sum (fp32 accum), stores fp16 sumfeat. Warp per pair.
// ---------------------------------------------------------------------------
__global__ __launch_bounds__(256) void k1_gather_h(const int* __restrict__ neighs) {
    const int tid  = threadIdx.x;
    const int warp = tid >> 5, lane = tid & 31;
    const int p = blockIdx.x * 8 + warp;
    const int myidx = neighs[p * 32 + lane];
    const float4* __restrict__ base = (const float4*)g_featsh;

    float acc[8];
    #pragma unroll
    for (int q = 0; q < 8; q++) acc[q] = 0.f;

    #pragma unroll
    for (int j = 0; j < NEIGH; j++) {
        const int n = __shfl_sync(0xffffffffu, myidx, j);
        const float4 v = base[n * 32 + lane];
        const half2* h2 = (const half2*)&v;
        #pragma unroll
        for (int q = 0; q < 4; q++) {
            const float2 f = __half22float2(h2[q]);
            acc[2 * q]     += f.x;
            acc[2 * q + 1] += f.y;
        }
    }
    uint4 o;
    o.x = h2u(acc[0], acc[1]); o.y = h2u(acc[2], acc[3]);
    o.z = h2u(acc[4], acc[5]); o.w = h2u(acc[6], acc[7]);
    *(uint4*)&g_sumfh[p * FEAT + lane * 8] = o;
}

// ---------------------------------------------------------------------------
// K2: per-layer GEMM h = sumfeat @ W_l via HMMA m16n8k16 with register-staged
// double buffering. grid (64, 4). block 256 (8 warps). M=64, N=128, K=256.
// ---------------------------------------------------------------------------
__global__ __launch_bounds__(256) void k2_gemm() {
    __shared__ __align__(16) __half Ah[64][72];    // 9216 B
    __shared__ __align__(16) __half Bh[64][136];   // 17408 B

    const int l  = blockIdx.y;
    const int bm = blockIdx.x;
    const int tid = threadIdx.x;
    const int w = tid >> 5, lane = tid & 31;
    const int m0 = (w & 3) * 16;
    const int n0 = (w >> 2) * 64;
    const int lq = lane >> 3, lr = lane & 7;
    const int g = lane >> 2, t = lane & 3;

    // staging indices
    const int uA0 = tid,        rA0 = uA0 >> 3, cA0 = uA0 & 7;
    const int uA1 = tid + 256,  rA1 = uA1 >> 3, cA1 = uA1 & 7;
    int rB[4], cB[4];
    #pragma unroll
    for (int i = 0; i < 4; i++) {
        const int u = tid + i * 256;
        rB[i] = u >> 4; cB[i] = u & 15;
    }
    const int pairA0 = (bm * 64 + rA0) * 4 + l;
    const int pairA1 = (bm * 64 + rA1) * 4 + l;
    const __half* __restrict__ netl = g_neth + l * FEAT * EMB;

    float acc[8][4];
    #pragma unroll
    for (int i = 0; i < 8; i++)
        #pragma unroll
        for (int j = 0; j < 4; j++) acc[i][j] = 0.f;

    uint4 pA0, pA1, pB[4];
    pA0 = *(const uint4*)&g_sumfh[pairA0 * FEAT + cA0 * 8];
    pA1 = *(const uint4*)&g_sumfh[pairA1 * FEAT + cA1 * 8];
    #pragma unroll
    for (int i = 0; i < 4; i++)
        pB[i] = *(const uint4*)&netl[rB[i] * EMB + cB[i] * 8];
    *(uint4*)&Ah[rA0][cA0 * 8] = pA0;
    *(uint4*)&Ah[rA1][cA1 * 8] = pA1;
    #pragma unroll
    for (int i = 0; i < 4; i++) *(uint4*)&Bh[rB[i]][cB[i] * 8] = pB[i];
    __syncthreads();

    for (int c = 0; c < 4; c++) {
        if (c < 3) {
            const int kb = (c + 1) * 64;
            pA0 = *(const uint4*)&g_sumfh[pairA0 * FEAT + kb + cA0 * 8];
            pA1 = *(const uint4*)&g_sumfh[pairA1 * FEAT + kb + cA1 * 8];
            #pragma unroll
            for (int i = 0; i < 4; i++)
                pB[i] = *(const uint4*)&netl[(kb + rB[i]) * EMB + cB[i] * 8];
        }
        #pragma unroll
        for (int ks = 0; ks < 4; ks++) {
            const int kc = ks * 16;
            uint32_t a0, a1, a2, a3;
            ldm4(a0, a1, a2, a3,
                 s2u(&Ah[m0 + lr + (lq & 1) * 8][kc + (lq >> 1) * 8]));
            #pragma unroll
            for (int jn = 0; jn < 4; jn++) {
                uint32_t b0, b1, b2, b3;
                ldm4t(b0, b1, b2, b3,
                      s2u(&Bh[kc + lr + (lq & 1) * 8][n0 + jn * 16 + (lq >> 1) * 8]));
                mma16816(acc[2 * jn],     a0, a1, a2, a3, b0, b1);
                mma16816(acc[2 * jn + 1], a0, a1, a2, a3, b2, b3);
            }
        }
        __syncthreads();
        if (c < 3) {
            *(uint4*)&Ah[rA0][cA0 * 8] = pA0;
            *(uint4*)&Ah[rA1][cA1 * 8] = pA1;
            #pragma unroll
            for (int i = 0; i < 4; i++) *(uint4*)&Bh[rB[i]][cB[i] * 8] = pB[i];
            __syncthreads();
        }
    }

    // epilogue: write fp32 + fp16 h
    #pragma unroll
    for (int jn2 = 0; jn2 < 8; jn2++) {
        const int col = n0 + jn2 * 8 + 2 * t;
        const int row0 = bm * 64 + m0 + g;
        const int pair0 = row0 * 4 + l;
        const int pair1 = (row0 + 8) * 4 + l;
        *(float2*)&g_h[pair0 * EMB + col] = make_float2(acc[jn2][0], acc[jn2][1]);
        *(float2*)&g_h[pair1 * EMB + col] = make_float2(acc[jn2][2], acc[jn2][3]);
        *(uint32_t*)&g_hh[pair0 * EMB + col] = h2u(acc[jn2][0], acc[jn2][1]);
        *(uint32_t*)&g_hh[pair1 * EMB + col] = h2u(acc[jn2][2], acc[jn2][3]);
    }
}

// ---------------------------------------------------------------------------
// K34: tile = 64 pairs (16 batch rows), grid 256 blocks, 256 threads.
// phase1: HMMA scores GEMM (unchanged).
// phase3: float4 agg.  phase4: shuffle-fed FFMA2 TW GEMM (warp = 4 rows x 64
// cols, aggs in registers, TW u64/lane from smem).  phase5: normalize.
// ---------------------------------------------------------------------------
__global__ __launch_bounds__(256) void k34_fused(const float* __restrict__ Ws2,
                                                 const float* __restrict__ TW,
                                                 const float* __restrict__ lemb,
                                                 const int* __restrict__ node_i,
                                                 const int* __restrict__ layers,
                                                 float* __restrict__ out) {
    __shared__ __align__(16) unsigned char SB[43904];
    __half (*Ah)[72]   = (__half(*)[72])(SB + 0);        // 9216  (phase1)
    __half (*Bh)[136]  = (__half(*)[136])(SB + 9216);    // 17408 (phase1)
    float (*Bs4)[132]  = (float(*)[132])(SB + 0);        // 33792 (phase4, reuse)
    float (*aggs)[132] = (float(*)[132])(SB + 33792);    // 8448  -> 42240
    float *scr         = (float*)(SB + 42240);           // 256
    float (*att)[4]    = (float(*)[4])(SB + 42496);      // 256
    float *w2s         = (float*)(SB + 42752);           // 512
    float (*red)[2]    = (float(*)[2])(SB + 43264);      // 512 (scores + norms)

    const int tid = threadIdx.x;
    const int bm = blockIdx.x;          // 256 blocks
    const int pb = bm * 64;             // pair base
    const int B0 = bm * 16;             // batch-row base

    const int w = tid >> 5, lane = tid & 31;
    const int m0 = (w & 3) * 16;
    const int nh = w >> 2;
    const int n0 = nh * 64;
    const int lq = lane >> 3, lr = lane & 7;
    const int g = lane >> 2, t = lane & 3;

    if (tid < 128) w2s[tid] = Ws2[tid];

    // staging indices (phase1)
    const int uA0 = tid,        rA0 = uA0 >> 3, cA0 = uA0 & 7;
    const int uA1 = tid + 256,  rA1 = uA1 >> 3, cA1 = uA1 & 7;
    int rB[4], cB[4];
    #pragma unroll
    for (int i = 0; i < 4; i++) {
        const int u = tid + i * 256;
        rB[i] = u >> 4; cB[i] = u & 15;
    }

    // ---- phase 1: HMMA GEMM h[64x128] @ Ws1[128x128], 2 K-chunks + prefetch --
    float acc[8][4];
    #pragma unroll
    for (int i = 0; i < 8; i++)
        #pragma unroll
        for (int j = 0; j < 4; j++) acc[i][j] = 0.f;

    uint4 pA0, pA1, pB[4];
    pA0 = *(const uint4*)&g_hh[(pb + rA0) * EMB + cA0 * 8];
    pA1 = *(const uint4*)&g_hh[(pb + rA1) * EMB + cA1 * 8];
    #pragma unroll
    for (int i = 0; i < 4; i++)
        pB[i] = *(const uint4*)&g_ws1h[rB[i] * EMB + cB[i] * 8];
    *(uint4*)&Ah[rA0][cA0 * 8] = pA0;
    *(uint4*)&Ah[rA1][cA1 * 8] = pA1;
    #pragma unroll
    for (int i = 0; i < 4; i++) *(uint4*)&Bh[rB[i]][cB[i] * 8] = pB[i];
    __syncthreads();

    for (int c = 0; c < 2; c++) {
        if (c < 1) {
            pA0 = *(const uint4*)&g_hh[(pb + rA0) * EMB + 64 + cA0 * 8];
            pA1 = *(const uint4*)&g_hh[(pb + rA1) * EMB + 64 + cA1 * 8];
            #pragma unroll
            for (int i = 0; i < 4; i++)
                pB[i] = *(const uint4*)&g_ws1h[(64 + rB[i]) * EMB + cB[i] * 8];
        }
        #pragma unroll
        for (int ks = 0; ks < 4; ks++) {
            const int kc = ks * 16;
            uint32_t a0, a1, a2, a3;
            ldm4(a0, a1, a2, a3,
                 s2u(&Ah[m0 + lr + (lq & 1) * 8][kc + (lq >> 1) * 8]));
            #pragma unroll
            for (int jn = 0; jn < 4; jn++) {
                uint32_t b0, b1, b2, b3;
                ldm4t(b0, b1, b2, b3,
                      s2u(&Bh[kc + lr + (lq & 1) * 8][n0 + jn * 16 + (lq >> 1) * 8]));
                mma16816(acc[2 * jn],     a0, a1, a2, a3, b0, b1);
                mma16816(acc[2 * jn + 1], a0, a1, a2, a3, b2, b3);
            }
        }
        __syncthreads();
        if (c < 1) {
            *(uint4*)&Ah[rA0][cA0 * 8] = pA0;
            *(uint4*)&Ah[rA1][cA1 * 8] = pA1;
            #pragma unroll
            for (int i = 0; i < 4; i++) *(uint4*)&Bh[rB[i]][cB[i] * 8] = pB[i];
            __syncthreads();
        }
    }
    // epilogue: tanh + dot with Ws2, reduce over quad lanes
    {
        float p0 = 0.f, p1 = 0.f;
        #pragma unroll
        for (int jn2 = 0; jn2 < 8; jn2++) {
            const int col = n0 + jn2 * 8 + 2 * t;
            p0 += tanhf(acc[jn2][0]) * w2s[col] + tanhf(acc[jn2][1]) * w2s[col + 1];
            p1 += tanhf(acc[jn2][2]) * w2s[col] + tanhf(acc[jn2][3]) * w2s[col + 1];
        }
        p0 += __shfl_xor_sync(0xffffffffu, p0, 1);
        p0 += __shfl_xor_sync(0xffffffffu, p0, 2);
        p1 += __shfl_xor_sync(0xffffffffu, p1, 1);
        p1 += __shfl_xor_sync(0xffffffffu, p1, 2);
        if (t == 0) {
            red[m0 + g][nh]     = p0;
            red[m0 + 8 + g][nh] = p1;
        }
    }
    __syncthreads();
    if (tid < 64) scr[tid] = red[tid][0] + red[tid][1];
    __syncthreads();

    // ---- phase 2: softmax over 4 layers (16 rows) ----
    if (tid < 16) {
        const float s0 = scr[tid * 4 + 0];
        const float s1 = scr[tid * 4 + 1];
        const float s2 = scr[tid * 4 + 2];
        const float s3 = scr[tid * 4 + 3];
        const float mx = fmaxf(fmaxf(s0, s1), fmaxf(s2, s3));
        const float e0 = __expf(s0 - mx), e1 = __expf(s1 - mx);
        const float e2 = __expf(s2 - mx), e3 = __expf(s3 - mx);
        const float inv = 1.f / (e0 + e1 + e2 + e3);
        att[tid][0] = e0 * inv; att[tid][1] = e1 * inv;
        att[tid][2] = e2 * inv; att[tid][3] = e3 * inv;
    }
    __syncthreads();

    // ---- phase 3: attention-weighted aggregation (float4 vectorized) ----
    {
        const int m4 = tid & 31;          // float4 column group
        const int bh = tid >> 5;          // 0..7 -> 2 rows each
        #pragma unroll
        for (int bb = 0; bb < 2; bb++) {
            const int b = bh * 2 + bb;
            const float4* hp = (const float4*)&g_h[(pb + b * 4) * EMB];
            const float4 v0 = hp[m4];
            const float4 v1 = hp[32 + m4];
            const float4 v2 = hp[64 + m4];
            const float4 v3 = hp[96 + m4];
            const float a0 = att[b][0], a1 = att[b][1];
            const float a2 = att[b][2], a3 = att[b][3];
            float4 r;
            r.x = fmaf(a3, v3.x, fmaf(a2, v2.x, fmaf(a1, v1.x, a0 * v0.x)));
            r.y = fmaf(a3, v3.y, fmaf(a2, v2.y, fmaf(a1, v1.y, a0 * v0.y)));
            r.z = fmaf(a3, v3.z, fmaf(a2, v2.z, fmaf(a1, v1.z, a0 * v0.z)));
            r.w = fmaf(a3, v3.w, fmaf(a2, v2.w, fmaf(a1, v1.w, a0 * v0.w)));
            *(float4*)&aggs[b][m4 * 4] = r;
        }
    }
    __syncthreads();

    // ---- phase 4: ne = agg @ TW via shuffle-fed FFMA2 ----
    // warp w: row group rg = w>>1 (4 rows), col half cg = w&1 (64 cols);
    // lane owns 2 cols (cg*64 + lane*2). aggs fed by register window + shfl.
    const int rg = w >> 1;
    const int cg = w & 1;
    u64 acc2[4];
    #pragma unroll
    for (int r = 0; r < 4; r++) acc2[r] = 0ull;

    for (int ch = 0; ch < 2; ch++) {
        // stage TW chunk [64 k][128 m]
        #pragma unroll
        for (int i = 0; i < 32; i++) {
            const int idx = tid + i * 256;
            const int f = idx >> 7, m = idx & 127;
            Bs4[f][m] = TW[(ch * 64 + f) * EMB + m];
        }
        __syncthreads();
        #pragma unroll
        for (int w0 = 0; w0 < 64; w0 += 32) {
            float aw0 = aggs[rg * 4 + 0][ch * 64 + w0 + lane];
            float aw1 = aggs[rg * 4 + 1][ch * 64 + w0 + lane];
            float aw2 = aggs[rg * 4 + 2][ch * 64 + w0 + lane];
            float aw3 = aggs[rg * 4 + 3][ch * 64 + w0 + lane];
            #pragma unroll
            for (int kk = 0; kk < 32; kk++) {
                const u64 wv = *(const u64*)&Bs4[w0 + kk][cg * 64 + lane * 2];
                const float a0 = __shfl_sync(0xffffffffu, aw0, kk);
                const float a1 = __shfl_sync(0xffffffffu, aw1, kk);
                const float a2 = __shfl_sync(0xffffffffu, aw2, kk);
                const float a3 = __shfl_sync(0xffffffffu, aw3, kk);
                acc2[0] = fma2(pack2(a0), wv, acc2[0]);
                acc2[1] = fma2(pack2(a1), wv, acc2[1]);
                acc2[2] = fma2(pack2(a2), wv, acc2[2]);
                acc2[3] = fma2(pack2(a3), wv, acc2[3]);
            }
        }
        __syncthreads();
    }

    // ---- phase 5: residual + L2 normalize ----
    float2 fv[4];
    #pragma unroll
    for (int r = 0; r < 4; r++) {
        const int bg = B0 + rg * 4 + r;
        const int li = node_i[bg] * 4 + layers[bg];
        const float2 lv = *(const float2*)&lemb[li * EMB + cg * 64 + lane * 2];
        const float2 f2 = unpk(acc2[r]);
        fv[r].x = f2.x + lv.x;
        fv[r].y = f2.y + lv.y;
        float v = fv[r].x * fv[r].x + fv[r].y * fv[r].y;
        #pragma unroll
        for (int off = 16; off > 0; off >>= 1)
            v += __shfl_xor_sync(0xffffffffu, v, off);
        if (lane == 0) red[rg * 4 + r][cg] = v;
    }
    __syncthreads();
    #pragma unroll
    for (int r = 0; r < 4; r++) {
        const int bg = B0 + rg * 4 + r;
        const float nrm = sqrtf(red[rg * 4 + r][0] + red[rg * 4 + r][1]);
        const float inv = 1.f / fmaxf(nrm, 1e-12f);
        float2 o;
        o.x = fv[r].x * inv; o.y = fv[r].y * inv;
        *(float2*)&out[bg * EMB + cg * 64 + lane * 2] = o;
    }
}

// ---------------------------------------------------------------------------
extern "C" void kernel_launch(void* const* d_in, const int* in_sizes, int n_in,
                              void* d_out, int out_size) {
    const int*   layers  = (const int*)d_in[0];
    const int*   node_i  = (const int*)d_in[1];
    const int*   neighs  = (const int*)d_in[2];
    const float* feats   = (const float*)d_in[3];
    const float* lemb    = (const float*)d_in[4];
    const float* net     = (const float*)d_in[5];
    const float* TW      = (const float*)d_in[6];
    const float* Ws1     = (const float*)d_in[7];
    const float* Ws2     = (const float*)d_in[8];
    float* out = (float*)d_out;

    k0_convert<<<2048, 256>>>(feats);
    k0b_convert<<<144, 256>>>(net, Ws1);
    k1_gather_h<<<PAIRS / 8, 256>>>(neighs);
    k2_gemm<<<dim3(BATCH / 64, LAYERS), 256>>>();
    k34_fused<<<PAIRS / 64, 256>>>(Ws2, TW, lemb, node_i, layers, out);
}